// round 8
// baseline (speedup 1.0000x reference)
#include <cuda_runtime.h>
#include <math.h>

#define BATCH 16
#define DIM 48
#define HID 16
#define CH 8
#define IMH 256
#define IMW 256
#define HXW (IMH*IMW)
#define NPIX (BATCH*HXW)          // 1,048,576
#define PADW 264                  // padded plane row stride (mult of 8 for float4 alignment)
#define PADH 258
#define PPLANE (PADH*PADW)        // 68112 (mult of 4)
#define NTHREADS 256
#define LUTN 4096
#define LUT_SCALE 256.0f          // segments per unit
#define LUT_BIAS  2048.0f         // index of v=0

// scratch: LN'd x2 in zero-padded planes [ch][b][258][264] (ring stays 0 => free 'SAME' pad)
__device__ __align__(16) float g_n[CH * BATCH * PPLANE];
// gate input x1 planar [ch][b][65536]
__device__ __align__(16) float g_x1[CH * BATCH * HXW];
// gelu(gelu(.)) lookup table: entry i = (f(x_i), f(x_{i+1})), x_i = -8 + i/256
__device__ __align__(16) float2 g_lut[LUTN];

typedef unsigned long long ull;

__device__ __forceinline__ ull bcast2(float a) {
    ull r; asm("mov.b64 %0, {%1, %1};" : "=l"(r) : "f"(a)); return r;
}
__device__ __forceinline__ void fma2(ull &d, ull a, ull b) {
    asm("fma.rn.f32x2 %0, %1, %2, %0;" : "+l"(d) : "l"(a), "l"(b));
}
__device__ __forceinline__ void unpack2(ull v, float &a, float &b) {
    asm("mov.b64 {%0, %1}, %2;" : "=f"(a), "=f"(b) : "l"(v));
}

__device__ __forceinline__ float gelu_exact(float v) {
    return 0.5f * v * (1.0f + erff(v * 0.70710678118654752f));
}

// ---------------- Kernel 0: build gelu(gelu()) LUT ----------------
__global__ void lut_init_kernel() {
    const int i = blockIdx.x * blockDim.x + threadIdx.x;   // 0..4095
    const float x0 = -8.0f + (float)i * (1.0f / LUT_SCALE);
    const float x1 = x0 + (1.0f / LUT_SCALE);
    g_lut[i] = make_float2(gelu_exact(gelu_exact(x0)),
                           gelu_exact(gelu_exact(x1)));
}

// ---------------- Kernel A: GEMM1 (packed f32x2) + LUT gelu^2 + LN, 2 px/thread ----------------
__global__ __launch_bounds__(NTHREADS)
void stage_a_kernel(const float* __restrict__ x,
                    const float* __restrict__ W1,
                    const float* __restrict__ b1,
                    const float* __restrict__ gamma,
                    const float* __restrict__ beta)
{
    __shared__ __align__(16) float sW1[DIM * HID];
    __shared__ __align__(16) float sb1[HID];
    __shared__ float sg[CH], sbt[CH];
    __shared__ __align__(16) float2 slut[LUTN];

    const int tid = threadIdx.x;
    for (int i = tid; i < DIM * HID; i += NTHREADS) sW1[i] = W1[i];
    if (tid < HID) sb1[tid] = b1[tid];
    if (tid < CH) { sg[tid] = gamma[tid]; sbt[tid] = beta[tid]; }
    {
        const float4* src = (const float4*)g_lut;
        float4* dst = (float4*)slut;
        #pragma unroll
        for (int i = 0; i < (LUTN * 2) / 4 / NTHREADS; i++)
            dst[tid + i * NTHREADS] = src[tid + i * NTHREADS];
    }
    __syncthreads();

    const int t  = blockIdx.x * NTHREADS + tid;
    const int p0 = t * 2;                      // two consecutive pixels, same row
    const int b   = p0 >> 16;
    const int pos = p0 & (HXW - 1);
    const int h = pos >> 8;
    const int w = pos & 255;

    const float4* __restrict__ tv0 = (const float4*)(x + (size_t)p0 * DIM);
    const float4* __restrict__ tv1 = (const float4*)(x + (size_t)(p0 + 1) * DIM);

    ull acc0[CH], acc1[CH];
    {
        const ull* sb1p = (const ull*)sb1;
        #pragma unroll
        for (int i = 0; i < CH; i++) { ull v = sb1p[i]; acc0[i] = v; acc1[i] = v; }
    }

    #pragma unroll
    for (int dq = 0; dq < DIM / 4; dq++) {
        const float4 a4 = tv0[dq];
        const float4 c4 = tv1[dq];
        const float av[4] = {a4.x, a4.y, a4.z, a4.w};
        const float cv[4] = {c4.x, c4.y, c4.z, c4.w};
        #pragma unroll
        for (int j = 0; j < 4; j++) {
            const ull ta = bcast2(av[j]);
            const ull tb = bcast2(cv[j]);
            const ull* wr = (const ull*)&sW1[(dq * 4 + j) * HID];
            #pragma unroll
            for (int i = 0; i < CH; i++) {
                const ull wv = wr[i];
                fma2(acc0[i], ta, wv);
                fma2(acc1[i], tb, wv);
            }
        }
    }

    #pragma unroll
    for (int px = 0; px < 2; px++) {
        float acc[HID];
        #pragma unroll
        for (int i = 0; i < CH; i++)
            unpack2(px == 0 ? acc0[i] : acc1[i], acc[2 * i], acc[2 * i + 1]);

        // gelu(gelu(.)) via piecewise-linear LUT, analytic tails
        #pragma unroll
        for (int hh = 0; hh < HID; hh++) {
            const float v = acc[hh];
            float tpos = fmaf(v, LUT_SCALE, LUT_BIAS);
            tpos = fminf(fmaxf(tpos, 0.0f), 4095.0f);
            const int idx = (int)tpos;
            const float fr = tpos - (float)idx;
            const float2 lv = slut[idx];
            float r = fmaf(lv.y - lv.x, fr, lv.x);
            r = (v > 8.0f)  ? v    : r;
            r = (v < -8.0f) ? 0.0f : r;
            acc[hh] = r;
        }

        float m = 0.0f;
        #pragma unroll
        for (int c = 0; c < CH; c++) m += acc[CH + c];
        m *= (1.0f / CH);
        float var = 0.0f;
        #pragma unroll
        for (int c = 0; c < CH; c++) { float d = acc[CH + c] - m; var += d * d; }
        var *= (1.0f / CH);
        const float inv = rsqrtf(var + 1e-5f);

        const int padidx = b * PPLANE + (h + 1) * PADW + (w + px + 1);
        #pragma unroll
        for (int c = 0; c < CH; c++)
            g_n[(size_t)c * (BATCH * PPLANE) + padidx] =
                (acc[CH + c] - m) * inv * sg[c] + sbt[c];

        #pragma unroll
        for (int c = 0; c < CH; c++)
            g_x1[(size_t)c * NPIX + p0 + px] = acc[c];
    }
}

// ---------------- Kernel B: conv + gate + GEMM2, 4 px/thread, vector loads ----------------
__global__ __launch_bounds__(NTHREADS, 2)
void stage_b_kernel(const float* __restrict__ dww,
                    const float* __restrict__ dwb,
                    const float* __restrict__ pww,
                    const float* __restrict__ pwb,
                    const float* __restrict__ W2,
                    const float* __restrict__ b2,
                    float* __restrict__ out)
{
    __shared__ float sW2[CH * DIM];
    __shared__ float sb2[DIM];
    __shared__ float sdw[CH * 9], sdwb[CH];
    __shared__ float spw[CH * CH], spwb[CH];

    const int tid = threadIdx.x;
    for (int i = tid; i < CH * DIM; i += NTHREADS) sW2[i] = W2[i];
    if (tid < DIM) sb2[tid] = b2[tid];
    if (tid < CH) { sdwb[tid] = dwb[tid]; spwb[tid] = pwb[tid]; }
    for (int i = tid; i < CH * 9;  i += NTHREADS) sdw[i] = dww[i];
    for (int i = tid; i < CH * CH; i += NTHREADS) spw[i] = pww[i];
    __syncthreads();

    const int t  = blockIdx.x * NTHREADS + tid;
    const int p0 = t * 4;                       // 4 consecutive pixels, same row
    const int b   = p0 >> 16;
    const int pos = p0 & (HXW - 1);
    const int h  = pos >> 8;
    const int w0 = pos & 255;                   // multiple of 4

    const int rb = b * PPLANE + h * PADW + w0;

    float sp[CH][4];     // depthwise results
    float nc[CH][4];     // center values (for pointwise)

    #pragma unroll
    for (int c = 0; c < CH; c++) {
        const float* __restrict__ np = &g_n[(size_t)c * (BATCH * PPLANE) + rb];

        const float4 r0a = *(const float4*)np;
        const float2 r0b = *(const float2*)(np + 4);
        const float4 r1a = *(const float4*)(np + PADW);
        const float2 r1b = *(const float2*)(np + PADW + 4);
        const float4 r2a = *(const float4*)(np + 2 * PADW);
        const float2 r2b = *(const float2*)(np + 2 * PADW + 4);

        const float v0[6] = {r0a.x, r0a.y, r0a.z, r0a.w, r0b.x, r0b.y};
        const float v1[6] = {r1a.x, r1a.y, r1a.z, r1a.w, r1b.x, r1b.y};
        const float v2[6] = {r2a.x, r2a.y, r2a.z, r2a.w, r2b.x, r2b.y};

        const float* kw = &sdw[c * 9];
        #pragma unroll
        for (int i = 0; i < 4; i++) {
            float s = sdwb[c];
            s += v0[i] * kw[0]; s += v0[i + 1] * kw[1]; s += v0[i + 2] * kw[2];
            s += v1[i] * kw[3]; s += v1[i + 1] * kw[4]; s += v1[i + 2] * kw[5];
            s += v2[i] * kw[6]; s += v2[i + 1] * kw[7]; s += v2[i + 2] * kw[8];
            sp[c][i] = s;
            nc[c][i] = v1[i + 1];
        }
    }

    float g[CH][4];
    #pragma unroll
    for (int c = 0; c < CH; c++) {
        float ch0 = spwb[c], ch1 = spwb[c], ch2 = spwb[c], ch3 = spwb[c];
        #pragma unroll
        for (int ci = 0; ci < CH; ci++) {
            const float wv = spw[c * CH + ci];
            ch0 += wv * nc[ci][0];
            ch1 += wv * nc[ci][1];
            ch2 += wv * nc[ci][2];
            ch3 += wv * nc[ci][3];
        }
        const float4 x1v = *(const float4*)&g_x1[(size_t)c * NPIX + p0];
        g[c][0] = x1v.x * sp[c][0] * ch0;
        g[c][1] = x1v.y * sp[c][1] * ch1;
        g[c][2] = x1v.z * sp[c][2] * ch2;
        g[c][3] = x1v.w * sp[c][3] * ch3;
    }

    float* __restrict__ outb = out + (size_t)b * (DIM * HXW) + pos;

    #pragma unroll
    for (int dc = 0; dc < DIM / 4; dc++) {
        float o[4][4];
        #pragma unroll
        for (int j = 0; j < 4; j++) {
            const float bv = sb2[dc * 4 + j];
            o[j][0] = bv; o[j][1] = bv; o[j][2] = bv; o[j][3] = bv;
        }
        #pragma unroll
        for (int c = 0; c < CH; c++) {
            #pragma unroll
            for (int j = 0; j < 4; j++) {
                const float wv = sW2[c * DIM + dc * 4 + j];
                o[j][0] += g[c][0] * wv;
                o[j][1] += g[c][1] * wv;
                o[j][2] += g[c][2] * wv;
                o[j][3] += g[c][3] * wv;
            }
        }
        #pragma unroll
        for (int j = 0; j < 4; j++) {
            float4 ov = {o[j][0], o[j][1], o[j][2], o[j][3]};
            *(float4*)(outb + (size_t)(dc * 4 + j) * HXW) = ov;
        }
    }
}

extern "C" void kernel_launch(void* const* d_in, const int* in_sizes, int n_in,
                              void* d_out, int out_size)
{
    const float* x     = (const float*)d_in[0];
    const float* W1    = (const float*)d_in[1];
    const float* b1    = (const float*)d_in[2];
    const float* gamma = (const float*)d_in[3];
    const float* beta  = (const float*)d_in[4];
    const float* dww   = (const float*)d_in[5];
    const float* dwb   = (const float*)d_in[6];
    const float* pww   = (const float*)d_in[7];
    const float* pwb   = (const float*)d_in[8];
    const float* W2    = (const float*)d_in[9];
    const float* b2    = (const float*)d_in[10];
    float* out = (float*)d_out;

    lut_init_kernel<<<LUTN / NTHREADS, NTHREADS>>>();
    stage_a_kernel<<<NPIX / 2 / NTHREADS, NTHREADS>>>(x, W1, b1, gamma, beta);
    stage_b_kernel<<<NPIX / 4 / NTHREADS, NTHREADS>>>(dww, dwb, pww, pwb, W2, b2, out);
}

// round 11
// speedup vs baseline: 1.0494x; 1.0494x over previous
#include <cuda_runtime.h>
#include <math.h>

#define BATCH 16
#define DIM 48
#define HID 16
#define CH 8
#define IMH 256
#define IMW 256
#define HXW (IMH*IMW)
#define NPIX (BATCH*HXW)          // 1,048,576
#define PADW 264                  // padded plane row stride
#define PADH 258
#define PPLANE (PADH*PADW)
#define NTHREADS 256

// scratch: LN'd x2 in zero-padded planes [ch][b][258][264]
// pixel (h,w) lives at padded (h+1, w+2); cols 0..1 and 258..263 stay zero,
// rows 0 and 257 stay zero => branchless 'SAME' padding.
__device__ __align__(16) float g_n[CH * BATCH * PPLANE];
// gate input x1 planar [ch][b][65536]
__device__ __align__(16) float g_x1[CH * BATCH * HXW];

typedef unsigned long long ull;

__device__ __forceinline__ ull bcast2(float a) {
    ull r; asm("mov.b64 %0, {%1, %1};" : "=l"(r) : "f"(a)); return r;
}
__device__ __forceinline__ void fma2(ull &d, ull a, ull b) {
    asm("fma.rn.f32x2 %0, %1, %2, %0;" : "+l"(d) : "l"(a), "l"(b));
}
__device__ __forceinline__ void unpack2(ull v, float &a, float &b) {
    asm("mov.b64 {%0, %1}, %2;" : "=f"(a), "=f"(b) : "l"(v));
}

__device__ __forceinline__ float gelu_exact(float v) {
    return 0.5f * v * (1.0f + erff(v * 0.70710678118654752f));
}

// ---------------- Kernel A: GEMM1 (packed f32x2) + gelu^2 + LN, 2 px/thread ----------------
__global__ __launch_bounds__(NTHREADS, 3)
void stage_a_kernel(const float* __restrict__ x,
                    const float* __restrict__ W1,
                    const float* __restrict__ b1,
                    const float* __restrict__ gamma,
                    const float* __restrict__ beta)
{
    __shared__ __align__(16) float sW1[DIM * HID];
    __shared__ __align__(16) float sb1[HID];
    __shared__ float sg[CH], sbt[CH];

    const int tid = threadIdx.x;
    for (int i = tid; i < DIM * HID; i += NTHREADS) sW1[i] = W1[i];
    if (tid < HID) sb1[tid] = b1[tid];
    if (tid < CH) { sg[tid] = gamma[tid]; sbt[tid] = beta[tid]; }
    __syncthreads();

    const int t  = blockIdx.x * NTHREADS + tid;
    const int p0 = t * 2;                      // two consecutive pixels, same row
    const int b   = p0 >> 16;
    const int pos = p0 & (HXW - 1);
    const int h = pos >> 8;
    const int w = pos & 255;                   // even

    const float4* __restrict__ tv0 = (const float4*)(x + (size_t)p0 * DIM);
    const float4* __restrict__ tv1 = (const float4*)(x + (size_t)(p0 + 1) * DIM);

    ull acc0[CH], acc1[CH];
    {
        const ull* sb1p = (const ull*)sb1;
        #pragma unroll
        for (int i = 0; i < CH; i++) { ull v = sb1p[i]; acc0[i] = v; acc1[i] = v; }
    }

    #pragma unroll
    for (int dq = 0; dq < DIM / 4; dq++) {
        const float4 a4 = tv0[dq];
        const float4 c4 = tv1[dq];
        const float av[4] = {a4.x, a4.y, a4.z, a4.w};
        const float cv[4] = {c4.x, c4.y, c4.z, c4.w};
        #pragma unroll
        for (int j = 0; j < 4; j++) {
            const ull ta = bcast2(av[j]);
            const ull tb = bcast2(cv[j]);
            const ull* wr = (const ull*)&sW1[(dq * 4 + j) * HID];
            #pragma unroll
            for (int i = 0; i < CH; i++) {
                const ull wv = wr[i];
                fma2(acc0[i], ta, wv);
                fma2(acc1[i], tb, wv);
            }
        }
    }

    // epilogue for both pixels, then paired stores
    float n0[CH], x10[CH], n1[CH], x11[CH];

    #pragma unroll
    for (int px = 0; px < 2; px++) {
        float acc[HID];
        #pragma unroll
        for (int i = 0; i < CH; i++)
            unpack2(px == 0 ? acc0[i] : acc1[i], acc[2 * i], acc[2 * i + 1]);

        #pragma unroll
        for (int hh = 0; hh < HID; hh++)
            acc[hh] = gelu_exact(gelu_exact(acc[hh]));

        float m = 0.0f;
        #pragma unroll
        for (int c = 0; c < CH; c++) m += acc[CH + c];
        m *= (1.0f / CH);
        float var = 0.0f;
        #pragma unroll
        for (int c = 0; c < CH; c++) { float d = acc[CH + c] - m; var += d * d; }
        var *= (1.0f / CH);
        const float inv = rsqrtf(var + 1e-5f);

        #pragma unroll
        for (int c = 0; c < CH; c++) {
            const float nv = (acc[CH + c] - m) * inv * sg[c] + sbt[c];
            if (px == 0) { n0[c] = nv; x10[c] = acc[c]; }
            else         { n1[c] = nv; x11[c] = acc[c]; }
        }
    }

    const int padidx = b * PPLANE + (h + 1) * PADW + (w + 2);   // even col -> 8B aligned
    #pragma unroll
    for (int c = 0; c < CH; c++)
        *(float2*)&g_n[(size_t)c * (BATCH * PPLANE) + padidx] = make_float2(n0[c], n1[c]);

    #pragma unroll
    for (int c = 0; c < CH; c++)
        *(float2*)&g_x1[(size_t)c * NPIX + p0] = make_float2(x10[c], x11[c]);
}

// ---------------- Kernel B: conv + gate + GEMM2, 4 px/thread, vector loads ----------------
__global__ __launch_bounds__(NTHREADS, 2)
void stage_b_kernel(const float* __restrict__ dww,
                    const float* __restrict__ dwb,
                    const float* __restrict__ pww,
                    const float* __restrict__ pwb,
                    const float* __restrict__ W2,
                    const float* __restrict__ b2,
                    float* __restrict__ out)
{
    __shared__ float sW2[CH * DIM];
    __shared__ float sb2[DIM];
    __shared__ float sdw[CH * 9], sdwb[CH];
    __shared__ float spw[CH * CH], spwb[CH];

    const int tid = threadIdx.x;
    for (int i = tid; i < CH * DIM; i += NTHREADS) sW2[i] = W2[i];
    if (tid < DIM) sb2[tid] = b2[tid];
    if (tid < CH) { sdwb[tid] = dwb[tid]; spwb[tid] = pwb[tid]; }
    for (int i = tid; i < CH * 9;  i += NTHREADS) sdw[i] = dww[i];
    for (int i = tid; i < CH * CH; i += NTHREADS) spw[i] = pww[i];
    __syncthreads();

    const int t  = blockIdx.x * NTHREADS + tid;
    const int p0 = t * 4;                       // 4 consecutive pixels, same row
    const int b   = p0 >> 16;
    const int pos = p0 & (HXW - 1);
    const int h  = pos >> 8;
    const int w0 = pos & 255;                   // multiple of 4

    // pixel (h, w0+i) center at padded (h+1, w0+i+2); need rows h..h+2, cols w0+1..w0+6
    // load cols w0..w0+7 as two aligned float4s per row
    const int rb = b * PPLANE + h * PADW + w0;

    float sp[CH][4];     // depthwise results
    float nc[CH][4];     // center values (for pointwise)

    #pragma unroll
    for (int c = 0; c < CH; c++) {
        const float* __restrict__ np = &g_n[(size_t)c * (BATCH * PPLANE) + rb];

        const float4 r0a = *(const float4*)np;
        const float4 r0b = *(const float4*)(np + 4);
        const float4 r1a = *(const float4*)(np + PADW);
        const float4 r1b = *(const float4*)(np + PADW + 4);
        const float4 r2a = *(const float4*)(np + 2 * PADW);
        const float4 r2b = *(const float4*)(np + 2 * PADW + 4);

        const float v0[8] = {r0a.x, r0a.y, r0a.z, r0a.w, r0b.x, r0b.y, r0b.z, r0b.w};
        const float v1[8] = {r1a.x, r1a.y, r1a.z, r1a.w, r1b.x, r1b.y, r1b.z, r1b.w};
        const float v2[8] = {r2a.x, r2a.y, r2a.z, r2a.w, r2b.x, r2b.y, r2b.z, r2b.w};

        const float* kw = &sdw[c * 9];
        #pragma unroll
        for (int i = 0; i < 4; i++) {
            float s = sdwb[c];
            s += v0[i + 1] * kw[0]; s += v0[i + 2] * kw[1]; s += v0[i + 3] * kw[2];
            s += v1[i + 1] * kw[3]; s += v1[i + 2] * kw[4]; s += v1[i + 3] * kw[5];
            s += v2[i + 1] * kw[6]; s += v2[i + 2] * kw[7]; s += v2[i + 3] * kw[8];
            sp[c][i] = s;
            nc[c][i] = v1[i + 2];
        }
    }

    float g[CH][4];
    #pragma unroll
    for (int c = 0; c < CH; c++) {
        float ch0 = spwb[c], ch1 = spwb[c], ch2 = spwb[c], ch3 = spwb[c];
        #pragma unroll
        for (int ci = 0; ci < CH; ci++) {
            const float wv = spw[c * CH + ci];
            ch0 += wv * nc[ci][0];
            ch1 += wv * nc[ci][1];
            ch2 += wv * nc[ci][2];
            ch3 += wv * nc[ci][3];
        }
        const float4 x1v = *(const float4*)&g_x1[(size_t)c * NPIX + p0];
        g[c][0] = x1v.x * sp[c][0] * ch0;
        g[c][1] = x1v.y * sp[c][1] * ch1;
        g[c][2] = x1v.z * sp[c][2] * ch2;
        g[c][3] = x1v.w * sp[c][3] * ch3;
    }

    float* __restrict__ outb = out + (size_t)b * (DIM * HXW) + pos;

    #pragma unroll
    for (int dc = 0; dc < DIM / 4; dc++) {
        float o[4][4];
        #pragma unroll
        for (int j = 0; j < 4; j++) {
            const float bv = sb2[dc * 4 + j];
            o[j][0] = bv; o[j][1] = bv; o[j][2] = bv; o[j][3] = bv;
        }
        #pragma unroll
        for (int c = 0; c < CH; c++) {
            #pragma unroll
            for (int j = 0; j < 4; j++) {
                const float wv = sW2[c * DIM + dc * 4 + j];
                o[j][0] += g[c][0] * wv;
                o[j][1] += g[c][1] * wv;
                o[j][2] += g[c][2] * wv;
                o[j][3] += g[c][3] * wv;
            }
        }
        #pragma unroll
        for (int j = 0; j < 4; j++) {
            float4 ov = {o[j][0], o[j][1], o[j][2], o[j][3]};
            *(float4*)(outb + (size_t)(dc * 4 + j) * HXW) = ov;
        }
    }
}

extern "C" void kernel_launch(void* const* d_in, const int* in_sizes, int n_in,
                              void* d_out, int out_size)
{
    const float* x     = (const float*)d_in[0];
    const float* W1    = (const float*)d_in[1];
    const float* b1    = (const float*)d_in[2];
    const float* gamma = (const float*)d_in[3];
    const float* beta  = (const float*)d_in[4];
    const float* dww   = (const float*)d_in[5];
    const float* dwb   = (const float*)d_in[6];
    const float* pww   = (const float*)d_in[7];
    const float* pwb   = (const float*)d_in[8];
    const float* W2    = (const float*)d_in[9];
    const float* b2    = (const float*)d_in[10];
    float* out = (float*)d_out;

    stage_a_kernel<<<NPIX / 2 / NTHREADS, NTHREADS>>>(x, W1, b1, gamma, beta);
    stage_b_kernel<<<NPIX / 4 / NTHREADS, NTHREADS>>>(dww, dwb, pww, pwb, W2, b2, out);
}